// round 8
// baseline (speedup 1.0000x reference)
#include <cuda_runtime.h>
#include <cstdint>

// CTC prefix beam search — bit-exact vs JAX reference.
// One warp per batch element; all state in registers + shfl.
// R8: branchless sorting-network top-8 (no REDUX, no clear branches):
//     per-lane Batcher sort + bitonic-split merges + 5-level shfl butterfly.

#define BATCH 1024
#define TT    128
#define CCC   63
#define VVV   62
#define WW    8
#define NEGF  (-1e30f)
#define HB1C  1000003u
#define HB2C  2654435761u
#define WPB   4
#define FULL  0xffffffffu

typedef unsigned long long u64;
typedef unsigned int u32;

__device__ __forceinline__ float lax_logaddexp(float a, float b) {
    float m = fmaxf(a, b);
    return m + log1pf(expf(-fabsf(a - b)));
}
__device__ __forceinline__ float seg_lse2(float a, float b) {
    float m = fmaxf(a, b);
    float s = expf(a - m) + expf(b - m);
    return logf(fmaxf(s, 1e-30f)) + m;
}
__device__ __forceinline__ u32 ord_of_float(float f) {
    u32 u = __float_as_uint(f);
    return (u & 0x80000000u) ? ~u : (u | 0x80000000u);
}
__device__ __forceinline__ float float_of_ord(u32 u) {
    return __uint_as_float((u & 0x80000000u) ? (u & 0x7fffffffu) : ~u);
}
__device__ __forceinline__ u64 kmax(u64 a, u64 b) { return a > b ? a : b; }
// descending compare-exchange: a keeps max, b keeps min (branchless SETP+SEL)
__device__ __forceinline__ void cex(u64& a, u64& b) {
    u64 mx = a > b ? a : b;
    u64 mn = a > b ? b : a;
    a = mx; b = mn;
}
// bitonic merge (desc) of a bitonic 8-seq in T[0..7] -> sorted desc
#define BMERGE8(T)                                                   \
    do {                                                             \
        cex(T[0], T[4]); cex(T[1], T[5]); cex(T[2], T[6]); cex(T[3], T[7]); \
        cex(T[0], T[2]); cex(T[1], T[3]); cex(T[4], T[6]); cex(T[5], T[7]); \
        cex(T[0], T[1]); cex(T[2], T[3]); cex(T[4], T[5]); cex(T[6], T[7]); \
    } while (0)

__global__ void ctc_beam_kernel(const float* __restrict__ logits,
                                float* __restrict__ out) {
    __shared__ unsigned short hist[WPB][TT * WW];  // (parent<<8)|(char+1)
    const int wip  = threadIdx.x >> 5;
    const int lane = threadIdx.x & 31;
    const int b    = blockIdx.x * WPB + wip;
    const float* base = logits + (size_t)b * TT * CCC;
    const float NINF = __int_as_float(0xff800000);

    // beam state (valid on lanes 0..7; lane j == beam j)
    u32 bm_h1 = 1u, bm_h2 = 1u;
    float bm_pb  = (lane == 0) ? 0.0f : NEGF;
    float bm_pnb = NEGF;
    int bm_last = -1, bm_len = 0;
    float bm_spb = NEGF, bm_mpnb = NEGF;

    const u32 Mlow = ((u32)lane << 5) - ((u32)lane << 10);
    const u32 ordDeadThr = ord_of_float(0.5f * NEGF);

    // softmax frame 0
    float lp0, lp1;
    {
        float cx0 = base[lane];
        float cx1 = (lane < 31) ? base[lane + 32] : NINF;
        u32 mo = __reduce_max_sync(FULL, ord_of_float(fmaxf(cx0, cx1)));
        float mx = float_of_ord(mo);
        float e0 = expf(cx0 - mx);
        float e1 = (lane < 31) ? expf(cx1 - mx) : 0.0f;
        float sm = e0 + e1;
        #pragma unroll
        for (int off = 16; off; off >>= 1)
            sm += __shfl_xor_sync(FULL, sm, off);
        float lse = logf(sm);
        lp0 = cx0 - mx - lse;
        lp1 = cx1 - mx - lse;
    }
    // prefetch frame 1
    float nx0 = base[CCC + lane];
    float nx1 = (lane < 31) ? base[CCC + lane + 32] : NINF;

    for (int t = 0; t < TT; ++t) {
        // ---- 2a: per-beam prep ----
        float lpBlank = __shfl_sync(FULL, lp1, 30);   // class 62
        int ls = (bm_last >= 0) ? (bm_last & 31) : 0;
        float v0 = __shfl_sync(FULL, lp0, ls);
        float v1 = __shfl_sync(FULL, lp1, ls);
        float lpLast = (bm_last >= 32) ? v1 : v0;

        int dup = 0;
        #pragma unroll
        for (int k = 0; k < 7; ++k) {
            u32 hk1 = __shfl_sync(FULL, bm_h1, k);
            u32 hk2 = __shfl_sync(FULL, bm_h2, k);
            if (k < lane && hk1 == bm_h1 && hk2 == bm_h2) dup = 1;
        }
        u32 dupmask = __ballot_sync(FULL, dup) & 0xFFu;

        float bm_ptot = lax_logaddexp(bm_pb, bm_pnb);
        bm_spb = bm_ptot + lpBlank;
        float bm_spnb = (bm_last >= 0) ? (bm_pnb + lpLast) : NEGF;

        // ---- 2b: inverted merge detection ----
        int msrc = -1;
        #pragma unroll
        for (int i = 0; i < WW; ++i) {
            u32 ih1 = __shfl_sync(FULL, bm_h1, i);
            u32 ih2 = __shfl_sync(FULL, bm_h2, i);
            u32 c1 = bm_h1 - ih1 * HB1C - 1u;
            if (!((dupmask >> i) & 1u) && c1 < (u32)VVV &&
                bm_h2 == ih2 * HB2C + c1 + 1u)
                msrc = i * 64 + (int)c1;
        }
        if (dup || lane >= WW) msrc = -1;

        // kill masks
        u32 killLo = dupmask, killHi = dupmask;
        #pragma unroll
        for (int j = 0; j < WW; ++j) {
            int ms = __shfl_sync(FULL, msrc, j);
            if (ms >= 0) {
                int mi = ms >> 6, mc = ms & 63;
                if (mc == lane) killLo |= 1u << mi;
                if (mc == lane + 32) killHi |= 1u << mi;
            }
        }

        // merged stay pnb
        {
            int mi = (msrc >= 0) ? (msrc >> 6) : 0;
            int mc = (msrc >= 0) ? (msrc & 63) : 0;
            float mpbv = __shfl_sync(FULL, bm_pb, mi);
            float mptv = __shfl_sync(FULL, bm_ptot, mi);
            int   mlv  = __shfl_sync(FULL, bm_last, mi);
            float w0 = __shfl_sync(FULL, lp0, mc & 31);
            float w1 = __shfl_sync(FULL, lp1, mc & 31);
            float lpc = (mc >= 32) ? w1 : w0;
            float bv = ((mc == mlv) ? mpbv : mptv) + lpc;
            bm_mpnb = (msrc >= 0) ? seg_lse2(bm_spnb, bv) : bm_spnb;
        }

        // stay key (slot 16): idx = lane (<8)
        float cs0 = dup ? NEGF : lax_logaddexp(bm_spb, bm_mpnb);
        u64 key16 = (lane < WW)
            ? (((u64)ord_of_float(cs0) << 32) |
               (u32)(((1023u << 10) + 16u) + Mlow))
            : 0ull;

        // ---- 3: extend keys ----
        u64 key[16];
        #pragma unroll
        for (int i = 0; i < WW; ++i) {
            int   ilast = __shfl_sync(FULL, bm_last, i);
            float ipb   = __shfl_sync(FULL, bm_pb, i);
            float ipt   = __shfl_sync(FULL, bm_ptot, i);
            float sl = ((lane == ilast) ? ipb : ipt) + lp0;
            if ((killLo >> i) & 1u) sl = NEGF;
            u32 lowl = (u32)(((u32)(1015 - 62 * i) << 10) + (u32)i) + Mlow;
            key[i] = ((u64)ord_of_float(sl) << 32) | lowl;
            float sh = ((lane + 32 == ilast) ? ipb : ipt) + lp1;
            if ((killHi >> i) & 1u) sh = NEGF;
            u32 lowh = (u32)(((u32)(983 - 62 * i) << 10) + (u32)(i + 8)) + Mlow;
            u64 kh = ((u64)ord_of_float(sh) << 32) | lowh;
            key[i + 8] = (lane < 30) ? kh : 0ull;
        }

        // ---- 3.5: OVERLAP — softmax of frame t+1 + prefetch t+2 ----
        float lpn0, lpn1;
        {
            u32 mo = __reduce_max_sync(FULL, ord_of_float(fmaxf(nx0, nx1)));
            float mx = float_of_ord(mo);
            float e0 = expf(nx0 - mx);
            float e1 = (lane < 31) ? expf(nx1 - mx) : 0.0f;
            float sm = e0 + e1;
            #pragma unroll
            for (int off = 16; off; off >>= 1)
                sm += __shfl_xor_sync(FULL, sm, off);
            float lse = logf(sm);
            lpn0 = nx0 - mx - lse;
            lpn1 = nx1 - mx - lse;
        }
        {
            int tn = (t + 2 < TT) ? (t + 2) : (TT - 1);
            const float* nf = base + tn * CCC;
            nx0 = nf[lane];
            nx1 = (lane < 31) ? nf[lane + 32] : NINF;
        }

        // ---- 4: top-8 via sorting networks (branchless, no REDUX) ----
        // 4a: Batcher sort (desc) key[0..7] and key[8..15], 19 CE each
        #define SORT8(K, O)                                                     \
            do {                                                                \
                cex(K[O+0],K[O+1]); cex(K[O+2],K[O+3]); cex(K[O+4],K[O+5]); cex(K[O+6],K[O+7]); \
                cex(K[O+0],K[O+2]); cex(K[O+1],K[O+3]); cex(K[O+4],K[O+6]); cex(K[O+5],K[O+7]); \
                cex(K[O+1],K[O+2]); cex(K[O+5],K[O+6]);                          \
                cex(K[O+0],K[O+4]); cex(K[O+1],K[O+5]); cex(K[O+2],K[O+6]); cex(K[O+3],K[O+7]); \
                cex(K[O+2],K[O+4]); cex(K[O+3],K[O+5]);                          \
                cex(K[O+1],K[O+2]); cex(K[O+3],K[O+4]); cex(K[O+5],K[O+6]);      \
            } while (0)
        SORT8(key, 0);
        SORT8(key, 8);
        // 4b: bitonic-split merge of the two sorted 8-lists -> top-8 (bitonic)
        u64 T[8];
        #pragma unroll
        for (int k = 0; k < 8; ++k) T[k] = kmax(key[k], key[15 - k]);
        BMERGE8(T);
        // 4c: fold in stay key (bitonic-split with [key16,0..0])
        T[7] = kmax(T[7], key16);
        BMERGE8(T);
        // 4d: 5-level cross-lane butterfly merge: after this every lane
        //     holds the global top-8 sorted descending.
        #pragma unroll
        for (int d = 1; d <= 16; d <<= 1) {
            u64 P[8];
            #pragma unroll
            for (int k = 0; k < 8; ++k)
                P[k] = __shfl_xor_sync(FULL, T[7 - k], d);
            #pragma unroll
            for (int k = 0; k < 8; ++k) T[k] = kmax(T[k], P[k]);
            BMERGE8(T);
        }
        // 4e: lane k takes winner k (static select tree on lane bits)
        u64 e0s = (lane & 1) ? T[1] : T[0];
        u64 e1s = (lane & 1) ? T[3] : T[2];
        u64 e2s = (lane & 1) ? T[5] : T[4];
        u64 e3s = (lane & 1) ? T[7] : T[6];
        u64 f0 = (lane & 2) ? e1s : e0s;
        u64 f1 = (lane & 2) ? e3s : e2s;
        u64 g  = (lane & 4) ? f1 : f0;
        u32 sel_m  = (u32)(g >> 32);
        u32 sel_lo = (u32)g;

        // ---- 5: commit (gathers via shfl from OLD beam regs) ----
        int idx  = 1023 - (int)(sel_lo >> 10);
        bool stay = idx < WW;
        int slot = (int)(sel_lo & 31u);
        int wl   = (int)((sel_lo >> 5) & 31u);
        int src  = stay ? idx : (slot & 7);
        int c    = wl + ((slot & 8) ? 32 : 0);
        u32 g_h1   = __shfl_sync(FULL, bm_h1, src);
        u32 g_h2   = __shfl_sync(FULL, bm_h2, src);
        int g_last = __shfl_sync(FULL, bm_last, src);
        int g_len  = __shfl_sync(FULL, bm_len, src);
        float g_spb  = __shfl_sync(FULL, bm_spb, src);
        float g_mpnb = __shfl_sync(FULL, bm_mpnb, src);
        if (lane < WW) {
            bool alive = sel_m > ordDeadThr;
            float score = float_of_ord(sel_m);
            float npb  = stay ? g_spb  : NEGF;
            float npnb = stay ? g_mpnb : score;
            if (!alive) { npb = NEGF; npnb = NEGF; }
            bm_pb = npb; bm_pnb = npnb;
            bm_h1 = stay ? g_h1 : (g_h1 * HB1C + (u32)(c + 1));
            bm_h2 = stay ? g_h2 : (g_h2 * HB2C + (u32)(c + 1));
            bm_last = stay ? g_last : c;
            bm_len  = g_len + (stay ? 0 : 1);
            hist[wip][t * WW + lane] = stay
                ? (unsigned short)(idx << 8)
                : (unsigned short)(((slot & 7) << 8) | (c + 1));
        }
        lp0 = lpn0; lp1 = lpn1;
    }

    // ---- outputs: decoded [B*128], lengths [B], prob [B], all f32 ----
    float* dec = out + (size_t)b * TT;
    #pragma unroll
    for (int s2 = 0; s2 < 4; ++s2)
        dec[lane + 32 * s2] = -1.0f;
    __syncwarp();
    int len0 = __shfl_sync(FULL, bm_len, 0);
    float pb0  = __shfl_sync(FULL, bm_pb, 0);
    float pnb0 = __shfl_sync(FULL, bm_pnb, 0);
    if (lane == 0) {
        int cur = 0;
        int pos = len0 - 1;
        for (int tt = TT - 1; tt >= 0; --tt) {
            unsigned short h = hist[wip][tt * WW + cur];
            int cc = (int)(h & 0xFF) - 1;
            cur = h >> 8;
            if (cc >= 0) dec[pos--] = (float)cc;
        }
        out[(size_t)BATCH * TT + b] = (float)len0;
        out[(size_t)BATCH * TT + BATCH + b] = expf(lax_logaddexp(pb0, pnb0));
    }
}

extern "C" void kernel_launch(void* const* d_in, const int* in_sizes, int n_in,
                              void* d_out, int out_size) {
    const float* logits = (const float*)d_in[0];
    float* out = (float*)d_out;
    ctc_beam_kernel<<<BATCH / WPB, 32 * WPB>>>(logits, out);
}

// round 10
// speedup vs baseline: 1.4843x; 1.4843x over previous
#include <cuda_runtime.h>
#include <cstdint>

// CTC prefix beam search — bit-exact vs JAX reference.
// One warp per batch element; all state in registers + shfl.
// R9/R10: local sorted top-8 (validated networks) + REDUX head-pop selection
//     (branchless), dup detection peeled to t=0 only, MUFU chains overlapped
//     with sort issue.

#define BATCH 1024
#define TT    128
#define CCC   63
#define VVV   62
#define WW    8
#define NEGF  (-1e30f)
#define HB1C  1000003u
#define HB2C  2654435761u
#define WPB   4
#define FULL  0xffffffffu

typedef unsigned long long u64;
typedef unsigned int u32;

__device__ __forceinline__ float lax_logaddexp(float a, float b) {
    float m = fmaxf(a, b);
    return m + log1pf(expf(-fabsf(a - b)));
}
__device__ __forceinline__ float seg_lse2(float a, float b) {
    float m = fmaxf(a, b);
    float s = expf(a - m) + expf(b - m);
    return logf(fmaxf(s, 1e-30f)) + m;
}
__device__ __forceinline__ u32 ord_of_float(float f) {
    u32 u = __float_as_uint(f);
    return (u & 0x80000000u) ? ~u : (u | 0x80000000u);
}
__device__ __forceinline__ float float_of_ord(u32 u) {
    return __uint_as_float((u & 0x80000000u) ? (u & 0x7fffffffu) : ~u);
}
__device__ __forceinline__ u64 kmax(u64 a, u64 b) { return a > b ? a : b; }
__device__ __forceinline__ void cex(u64& a, u64& b) {
    u64 mx = a > b ? a : b;
    u64 mn = a > b ? b : a;
    a = mx; b = mn;
}
// bitonic merge (desc) of a bitonic 8-seq -> sorted desc (validated R8)
#define BMERGE8(T)                                                   \
    do {                                                             \
        cex(T[0], T[4]); cex(T[1], T[5]); cex(T[2], T[6]); cex(T[3], T[7]); \
        cex(T[0], T[2]); cex(T[1], T[3]); cex(T[4], T[6]); cex(T[5], T[7]); \
        cex(T[0], T[1]); cex(T[2], T[3]); cex(T[4], T[5]); cex(T[6], T[7]); \
    } while (0)
// Batcher 19-CE sort (desc) of 8 (validated R8)
#define SORT8(K, O)                                                     \
    do {                                                                \
        cex(K[O+0],K[O+1]); cex(K[O+2],K[O+3]); cex(K[O+4],K[O+5]); cex(K[O+6],K[O+7]); \
        cex(K[O+0],K[O+2]); cex(K[O+1],K[O+3]); cex(K[O+4],K[O+6]); cex(K[O+5],K[O+7]); \
        cex(K[O+1],K[O+2]); cex(K[O+5],K[O+6]);                          \
        cex(K[O+0],K[O+4]); cex(K[O+1],K[O+5]); cex(K[O+2],K[O+6]); cex(K[O+3],K[O+7]); \
        cex(K[O+2],K[O+4]); cex(K[O+3],K[O+5]);                          \
        cex(K[O+1],K[O+2]); cex(K[O+3],K[O+4]); cex(K[O+5],K[O+6]);      \
    } while (0)

__global__ void ctc_beam_kernel(const float* __restrict__ logits,
                                float* __restrict__ out) {
    __shared__ unsigned short hist[WPB][TT * WW];  // (parent<<8)|(char+1)
    const int wip  = threadIdx.x >> 5;
    const int lane = threadIdx.x & 31;
    const int b    = blockIdx.x * WPB + wip;
    const float* base = logits + (size_t)b * TT * CCC;
    const float NINF = __int_as_float(0xff800000);

    // beam state (valid on lanes 0..7; lane j == beam j)
    u32 bm_h1 = 1u, bm_h2 = 1u;
    float bm_pb  = (lane == 0) ? 0.0f : NEGF;
    float bm_pnb = NEGF;
    int bm_last = -1, bm_len = 0;
    float bm_spb = NEGF, bm_mpnb = NEGF;

    const u32 Mlow = ((u32)lane << 5) - ((u32)lane << 10);
    const u32 ordDeadThr = ord_of_float(0.5f * NEGF);

    // softmax frame 0
    float lp0, lp1;
    {
        float cx0 = base[lane];
        float cx1 = (lane < 31) ? base[lane + 32] : NINF;
        u32 mo = __reduce_max_sync(FULL, ord_of_float(fmaxf(cx0, cx1)));
        float mx = float_of_ord(mo);
        float e0 = expf(cx0 - mx);
        float e1 = (lane < 31) ? expf(cx1 - mx) : 0.0f;
        float sm = e0 + e1;
        #pragma unroll
        for (int off = 16; off; off >>= 1)
            sm += __shfl_xor_sync(FULL, sm, off);
        float lse = logf(sm);
        lp0 = cx0 - mx - lse;
        lp1 = cx1 - mx - lse;
    }
    // prefetch frame 1
    float nx0 = base[CCC + lane];
    float nx1 = (lane < 31) ? base[CCC + lane + 32] : NINF;

    // duplicates exist ONLY at t=0 (beams 1..7 copy beam 0's empty prefix);
    // from t>=1 the selected beams are distinct hash-segments by construction
    // (>=63 finite-score distinct segments exist every step, so all 8 winners
    // are finite and distinct).
    u32 dupmask = 0xFEu;

    for (int t = 0; t < TT; ++t) {
        int dup = (int)((dupmask >> lane) & 1u);

        // ---- 2a: per-beam prep ----
        float lpBlank = __shfl_sync(FULL, lp1, 30);   // class 62
        int ls = (bm_last >= 0) ? (bm_last & 31) : 0;
        float v0 = __shfl_sync(FULL, lp0, ls);
        float v1 = __shfl_sync(FULL, lp1, ls);
        float lpLast = (bm_last >= 32) ? v1 : v0;

        float bm_ptot = lax_logaddexp(bm_pb, bm_pnb);
        bm_spb = bm_ptot + lpBlank;
        float bm_spnb = (bm_last >= 0) ? (bm_pnb + lpLast) : NEGF;

        // ---- 2b: inverted merge detection ----
        int msrc = -1;
        #pragma unroll
        for (int i = 0; i < WW; ++i) {
            u32 ih1 = __shfl_sync(FULL, bm_h1, i);
            u32 ih2 = __shfl_sync(FULL, bm_h2, i);
            u32 c1 = bm_h1 - ih1 * HB1C - 1u;
            if (!((dupmask >> i) & 1u) && c1 < (u32)VVV &&
                bm_h2 == ih2 * HB2C + c1 + 1u)
                msrc = i * 64 + (int)c1;
        }
        if (dup || lane >= WW) msrc = -1;

        // kill masks: bit i -> extend (beam i, class lane[/+32]) merged or dup
        u32 killLo = dupmask, killHi = dupmask;
        #pragma unroll
        for (int j = 0; j < WW; ++j) {
            int ms = __shfl_sync(FULL, msrc, j);
            if (ms >= 0) {
                int mi = ms >> 6, mc = ms & 63;
                if (mc == lane) killLo |= 1u << mi;
                if (mc == lane + 32) killHi |= 1u << mi;
            }
        }

        // ---- 3: extend keys (issue first; MUFU chain below overlaps sort) ----
        u64 key[16];
        #pragma unroll
        for (int i = 0; i < WW; ++i) {
            int   ilast = __shfl_sync(FULL, bm_last, i);
            float ipb   = __shfl_sync(FULL, bm_pb, i);
            float ipt   = __shfl_sync(FULL, bm_ptot, i);
            float sl = ((lane == ilast) ? ipb : ipt) + lp0;
            if ((killLo >> i) & 1u) sl = NEGF;
            u32 lowl = (u32)(((u32)(1015 - 62 * i) << 10) + (u32)i) + Mlow;
            key[i] = ((u64)ord_of_float(sl) << 32) | lowl;
            float sh = ((lane + 32 == ilast) ? ipb : ipt) + lp1;
            if ((killHi >> i) & 1u) sh = NEGF;
            u32 lowh = (u32)(((u32)(983 - 62 * i) << 10) + (u32)(i + 8)) + Mlow;
            u64 kh = ((u64)ord_of_float(sh) << 32) | lowh;
            key[i + 8] = (lane < 30) ? kh : 0ull;
        }

        // local sort of extends: two sorted 8-lists -> bitonic-split top-8
        SORT8(key, 0);
        SORT8(key, 8);
        u64 T[8];
        #pragma unroll
        for (int k = 0; k < 8; ++k) T[k] = kmax(key[k], key[15 - k]);
        BMERGE8(T);

        // merged stay pnb (MUFU chain; overlaps the sort issue above)
        {
            int mi = (msrc >= 0) ? (msrc >> 6) : 0;
            int mc = (msrc >= 0) ? (msrc & 63) : 0;
            float mpbv = __shfl_sync(FULL, bm_pb, mi);
            float mptv = __shfl_sync(FULL, bm_ptot, mi);
            int   mlv  = __shfl_sync(FULL, bm_last, mi);
            float w0 = __shfl_sync(FULL, lp0, mc & 31);
            float w1 = __shfl_sync(FULL, lp1, mc & 31);
            float lpc = (mc >= 32) ? w1 : w0;
            float bv = ((mc == mlv) ? mpbv : mptv) + lpc;
            bm_mpnb = (msrc >= 0) ? seg_lse2(bm_spnb, bv) : bm_spnb;
        }
        // stay key (slot 16): idx = lane (<8); insert into sorted list
        float cs0 = dup ? NEGF : lax_logaddexp(bm_spb, bm_mpnb);
        u64 key16 = (lane < WW)
            ? (((u64)ord_of_float(cs0) << 32) |
               (u32)(((1023u << 10) + 16u) + Mlow))
            : 0ull;
        T[7] = kmax(T[7], key16);
        BMERGE8(T);          // T = local top-8 sorted desc

        // ---- 3.5: OVERLAP — softmax of frame t+1 + prefetch t+2 ----
        float lpn0, lpn1;
        {
            u32 mo = __reduce_max_sync(FULL, ord_of_float(fmaxf(nx0, nx1)));
            float mx = float_of_ord(mo);
            float e0 = expf(nx0 - mx);
            float e1 = (lane < 31) ? expf(nx1 - mx) : 0.0f;
            float sm = e0 + e1;
            #pragma unroll
            for (int off = 16; off; off >>= 1)
                sm += __shfl_xor_sync(FULL, sm, off);
            float lse = logf(sm);
            lpn0 = nx0 - mx - lse;
            lpn1 = nx1 - mx - lse;
        }
        {
            int tn = (t + 2 < TT) ? (t + 2) : (TT - 1);
            const float* nf = base + tn * CCC;
            nx0 = nf[lane];
            nx1 = (lane < 31) ? nf[lane + 32] : NINF;
        }

        // ---- 4: top-8 via REDUX head-pop (branchless) ----
        u32 sel_m = 0u, sel_lo = 0u;   // lane k holds pass-k winner
        #pragma unroll
        for (int k2 = 0; k2 < WW; ++k2) {
            u32 hi = (u32)(T[0] >> 32), lo = (u32)T[0];
            u32 m  = __reduce_max_sync(FULL, hi);
            u32 tx = (hi == m) ? lo : 0u;
            u32 lw = __reduce_max_sync(FULL, tx);
            if (lane == k2) { sel_m = m; sel_lo = lw; }
            bool p = (lane == (int)((lw >> 5) & 31u));  // unique winner lane
            #pragma unroll
            for (int k = 0; k < 7; ++k) T[k] = p ? T[k + 1] : T[k];
            T[7] = p ? 0ull : T[7];
        }

        // ---- 5: commit (gathers via shfl from OLD beam regs) ----
        int idx  = 1023 - (int)(sel_lo >> 10);
        bool stay = idx < WW;
        int slot = (int)(sel_lo & 31u);
        int wl   = (int)((sel_lo >> 5) & 31u);
        int src  = stay ? idx : (slot & 7);
        int c    = wl + ((slot & 8) ? 32 : 0);
        u32 g_h1   = __shfl_sync(FULL, bm_h1, src);
        u32 g_h2   = __shfl_sync(FULL, bm_h2, src);
        int g_last = __shfl_sync(FULL, bm_last, src);
        int g_len  = __shfl_sync(FULL, bm_len, src);
        float g_spb  = __shfl_sync(FULL, bm_spb, src);
        float g_mpnb = __shfl_sync(FULL, bm_mpnb, src);
        if (lane < WW) {
            bool alive = sel_m > ordDeadThr;
            float score = float_of_ord(sel_m);
            float npb  = stay ? g_spb  : NEGF;
            float npnb = stay ? g_mpnb : score;
            if (!alive) { npb = NEGF; npnb = NEGF; }
            bm_pb = npb; bm_pnb = npnb;
            bm_h1 = stay ? g_h1 : (g_h1 * HB1C + (u32)(c + 1));
            bm_h2 = stay ? g_h2 : (g_h2 * HB2C + (u32)(c + 1));
            bm_last = stay ? g_last : c;
            bm_len  = g_len + (stay ? 0 : 1);
            hist[wip][t * WW + lane] = stay
                ? (unsigned short)(idx << 8)
                : (unsigned short)(((slot & 7) << 8) | (c + 1));
        }
        lp0 = lpn0; lp1 = lpn1;
        dupmask = 0u;          // duplicates only possible at t=0
    }

    // ---- outputs: decoded [B*128], lengths [B], prob [B], all f32 ----
    float* dec = out + (size_t)b * TT;
    #pragma unroll
    for (int s2 = 0; s2 < 4; ++s2)
        dec[lane + 32 * s2] = -1.0f;
    __syncwarp();
    int len0 = __shfl_sync(FULL, bm_len, 0);
    float pb0  = __shfl_sync(FULL, bm_pb, 0);
    float pnb0 = __shfl_sync(FULL, bm_pnb, 0);
    if (lane == 0) {
        int cur = 0;
        int pos = len0 - 1;
        for (int tt = TT - 1; tt >= 0; --tt) {
            unsigned short h = hist[wip][tt * WW + cur];
            int cc = (int)(h & 0xFF) - 1;
            cur = h >> 8;
            if (cc >= 0) dec[pos--] = (float)cc;
        }
        out[(size_t)BATCH * TT + b] = (float)len0;
        out[(size_t)BATCH * TT + BATCH + b] = expf(lax_logaddexp(pb0, pnb0));
    }
}

extern "C" void kernel_launch(void* const* d_in, const int* in_sizes, int n_in,
                              void* d_out, int out_size) {
    const float* logits = (const float*)d_in[0];
    float* out = (float*)d_out;
    ctc_beam_kernel<<<BATCH / WPB, 32 * WPB>>>(logits, out);
}